// round 17
// baseline (speedup 1.0000x reference)
#include <cuda_runtime.h>
#include <cuda_bf16.h>
#include <cuda_fp16.h>
#include <cstdint>

// ---------------- Problem constants ----------------
#define EMBED   256
#define HEADS   8
#define LEVELS  4
#define POINTS  4
#define CDIM    32
#define LEN_V   5440
#define LEN_Q   5440
#define BSZ     4
#define MROWS   (BSZ * LEN_Q)   // 21760

// ---------------- Scratch ----------------
__device__ __half g_vh [(size_t)MROWS * EMBED];   // projected value, fp16
__device__ float  g_off[(size_t)MROWS * EMBED];
__device__ float  g_awl[(size_t)MROWS * 128];

__device__ __half g_af0[(size_t)MROWS * EMBED];   // value fp16, later samp fp16
__device__ __half g_af1[(size_t)MROWS * EMBED];   // query fp16

// fp16 transposed weights [N,K]: vproj:0, off:65536, attn:131072, out:163840
__device__ __half g_wh[229376];

// ---------------- PTX helpers (generic ISA only) ----------------
__device__ __forceinline__ uint32_t smem_u32(const void* p) {
    uint32_t a;
    asm("{ .reg .u64 t; cvta.to.shared.u64 t, %1; cvt.u32.u64 %0, t; }" : "=r"(a) : "l"(p));
    return a;
}
__device__ __forceinline__ void ldm_x4(uint32_t* r, uint32_t addr) {
    asm volatile("ldmatrix.sync.aligned.m8n8.x4.shared.b16 {%0,%1,%2,%3}, [%4];"
        : "=r"(r[0]), "=r"(r[1]), "=r"(r[2]), "=r"(r[3]) : "r"(addr));
}
__device__ __forceinline__ void mma_f16(float* c, const uint32_t* a, const uint32_t* b) {
    asm volatile(
        "mma.sync.aligned.m16n8k16.row.col.f32.f16.f16.f32 "
        "{%0,%1,%2,%3}, {%4,%5,%6,%7}, {%8,%9}, {%0,%1,%2,%3};"
        : "+f"(c[0]), "+f"(c[1]), "+f"(c[2]), "+f"(c[3])
        : "r"(a[0]), "r"(a[1]), "r"(a[2]), "r"(a[3]), "r"(b[0]), "r"(b[1]));
}
__device__ __forceinline__ void cp16(uint32_t dst, const void* src) {
    asm volatile("cp.async.cg.shared.global [%0], [%1], 16;" :: "r"(dst), "l"(src));
}
#define CP_COMMIT() asm volatile("cp.async.commit_group;" ::: "memory")

// swizzled smem offset (16-bit elements): row stride 64, 16B chunk xor (row&7)
__device__ __forceinline__ int swz(int row, int k) {
    return row * 64 + ((((k >> 3) ^ row) & 7) << 3) + (k & 7);
}

// stage: A 128x64 halves (16KB) @0, B 128x64 halves (16KB) @16384
#define STAGE_B   32768
#define GEMM_SMEM (2 * STAGE_B)   // 64 KB

// ====================== shared GEMM mainloop =================================
// BM=128, BN=128, BK=64, 256 thr = 8 warps (4m x 2n), warp tile 32x64.
// 2-stage cp.async pipeline; single-buffered fragments (DB proven neutral).
struct GemmCtx {
    float c[2][8][4];   // [m16 tile][n8 tile][frag]
};

__device__ __forceinline__ void gemm_mainloop(
    GemmCtx& G, uint32_t uS,
    const __half* __restrict__ pA, const __half* __restrict__ pB,
    int tid, int lane, int wm, int wn)
{
    const int grow = tid >> 3;
    const int gc8  = tid & 7;

    #pragma unroll
    for (int mt = 0; mt < 2; ++mt)
        #pragma unroll
        for (int nt = 0; nt < 8; ++nt)
            #pragma unroll
            for (int i = 0; i < 4; ++i) G.c[mt][nt][i] = 0.f;

    auto stage_load = [&](int kc, int s) {
        const uint32_t sb = uS + s * STAGE_B;
        #pragma unroll
        for (int t = 0; t < 4; ++t) {
            const int row = grow + t * 32;
            const uint32_t so = (uint32_t)swz(row, gc8 * 8) * 2;
            cp16(sb + so,         pA + (size_t)row * EMBED + kc * 64 + gc8 * 8);
            cp16(sb + 16384 + so, pB + (size_t)row * EMBED + kc * 64 + gc8 * 8);
        }
        CP_COMMIT();
    };

    const int a_r = (lane & 15);
    const int a_k = (lane >> 4) << 3;
    const int b_n = ((lane >> 4) << 3) + (lane & 7);
    const int b_k = ((lane >> 3) & 1) << 3;

    stage_load(0, 0);
    stage_load(1, 1);
    #pragma unroll
    for (int kc = 0; kc < 4; ++kc) {
        const int s = kc & 1;
        if (kc < 2) {
            asm volatile("cp.async.wait_group 1;" ::: "memory");
        } else {
            asm volatile("cp.async.wait_group 0;" ::: "memory");
        }
        __syncthreads();

        const uint32_t uA = uS + s * STAGE_B;
        const uint32_t uB = uA + 16384;

        #pragma unroll
        for (int ks = 0; ks < 4; ++ks) {
            uint32_t a[2][4], b[8][2];
            #pragma unroll
            for (int mt = 0; mt < 2; ++mt)
                ldm_x4(a[mt], uA + swz(wm * 32 + mt * 16 + a_r, ks * 16 + a_k) * 2);
            #pragma unroll
            for (int np = 0; np < 4; ++np) {
                uint32_t t4[4];
                ldm_x4(t4, uB + swz(wn * 64 + np * 16 + b_n, ks * 16 + b_k) * 2);
                b[np * 2 + 0][0] = t4[0]; b[np * 2 + 0][1] = t4[1];
                b[np * 2 + 1][0] = t4[2]; b[np * 2 + 1][1] = t4[3];
            }
            #pragma unroll
            for (int mt = 0; mt < 2; ++mt)
                #pragma unroll
                for (int nt = 0; nt < 8; ++nt)
                    mma_f16(G.c[mt][nt], a[mt], b[nt]);
        }
        __syncthreads();
        if (kc < 2) stage_load(kc + 2, s);
    }
}

// ====================== merged projection GEMM ==============================
// grid (MROWS/128, 5): y<2 value->g_vh fp16 (cols y*128); y in [2,4)
// query->g_off fp32; y==4 query->g_awl fp32 (128 cols).
__global__ __launch_bounds__(256, 2)
void gemm_proj(const __half* __restrict__ A0, const __half* __restrict__ A1,
               const __half* __restrict__ Wh,
               const float* __restrict__ bV, const float* __restrict__ bO,
               const float* __restrict__ bA)
{
    extern __shared__ char sm[];
    const uint32_t uS = smem_u32(sm);

    const int tid  = threadIdx.x;
    const int lane = tid & 31;
    const int wid  = tid >> 5;
    const int wm   = wid & 3;
    const int wn   = wid >> 2;
    const int bm   = blockIdx.x * 128;
    const int by   = blockIdx.y;

    const __half* pA = ((by < 2) ? A0 : A1) + (size_t)bm * EMBED;
    const __half* pB = (by < 2) ? (Wh + (size_t)by * 128 * 256)
                     : (by < 4) ? (Wh + 65536 + (size_t)(by - 2) * 128 * 256)
                                : (Wh + 131072);

    GemmCtx G;
    gemm_mainloop(G, uS, pA, pB, tid, lane, wm, wn);

    if (by < 2) {
        const int colbase = by * 128;
        #pragma unroll
        for (int mt = 0; mt < 2; ++mt) {
            const int r0 = bm + wm * 32 + mt * 16 + (lane >> 2);
            #pragma unroll
            for (int nt = 0; nt < 8; ++nt) {
                const int col = colbase + wn * 64 + nt * 8 + (lane & 3) * 2;
                const float2 bv = *(const float2*)(bV + col);
                *(__half2*)(g_vh + (size_t)r0 * 256 + col) =
                    __floats2half2_rn(G.c[mt][nt][0] + bv.x, G.c[mt][nt][1] + bv.y);
                *(__half2*)(g_vh + (size_t)(r0 + 8) * 256 + col) =
                    __floats2half2_rn(G.c[mt][nt][2] + bv.x, G.c[mt][nt][3] + bv.y);
            }
        }
    } else {
        const bool isOff = (by < 4);
        float* Cf = isOff ? g_off : g_awl;
        const float* bs = isOff ? bO : bA;
        const int Nt = isOff ? 256 : 128;
        const int colbase = isOff ? (by - 2) * 128 : 0;
        #pragma unroll
        for (int mt = 0; mt < 2; ++mt) {
            const int r0 = bm + wm * 32 + mt * 16 + (lane >> 2);
            #pragma unroll
            for (int nt = 0; nt < 8; ++nt) {
                const int col = colbase + wn * 64 + nt * 8 + (lane & 3) * 2;
                const float2 bv = *(const float2*)(bs + col);
                *(float2*)(Cf + (size_t)r0 * Nt + col) =
                    make_float2(G.c[mt][nt][0] + bv.x, G.c[mt][nt][1] + bv.y);
                *(float2*)(Cf + (size_t)(r0 + 8) * Nt + col) =
                    make_float2(G.c[mt][nt][2] + bv.x, G.c[mt][nt][3] + bv.y);
            }
        }
    }
}

// ====================== out-proj GEMM (grid (170, 2)) =======================
__global__ __launch_bounds__(256, 2)
void gemm_out(const __half* __restrict__ A, const __half* __restrict__ BT,
              const float* __restrict__ bias, float* __restrict__ C)
{
    extern __shared__ char sm[];
    const uint32_t uS = smem_u32(sm);

    const int tid  = threadIdx.x;
    const int lane = tid & 31;
    const int wid  = tid >> 5;
    const int wm   = wid & 3;
    const int wn   = wid >> 2;
    const int bm   = blockIdx.x * 128;
    const int bn   = blockIdx.y * 128;

    GemmCtx G;
    gemm_mainloop(G, uS, A + (size_t)bm * EMBED, BT + (size_t)bn * EMBED,
                  tid, lane, wm, wn);

    #pragma unroll
    for (int mt = 0; mt < 2; ++mt) {
        const int r0 = bm + wm * 32 + mt * 16 + (lane >> 2);
        #pragma unroll
        for (int nt = 0; nt < 8; ++nt) {
            const int col = bn + wn * 64 + nt * 8 + (lane & 3) * 2;
            const float2 bv = *(const float2*)(bias + col);
            *(float2*)(C + (size_t)r0 * 256 + col) =
                make_float2(G.c[mt][nt][0] + bv.x, G.c[mt][nt][1] + bv.y);
            *(float2*)(C + (size_t)(r0 + 8) * 256 + col) =
                make_float2(G.c[mt][nt][2] + bv.x, G.c[mt][nt][3] + bv.y);
        }
    }
}

// ---------------- fused conversions (acts + weight transpose) ----------------
__global__ __launch_bounds__(256)
void conv_fuse(const float* __restrict__ value, const float* __restrict__ query,
               __half* __restrict__ d0, __half* __restrict__ d1,
               const float* __restrict__ w0, const float* __restrict__ w1,
               const float* __restrict__ w2, const float* __restrict__ w3)
{
    const int bx = blockIdx.x;
    if (bx < 10880) {
        const float* s = (bx < 5440) ? value : query;
        __half* d = (bx < 5440) ? d0 : d1;
        const size_t i = (size_t)(bx % 5440) * 256 + threadIdx.x;
        float4 x = ((const float4*)s)[i];
        union { __half2 h[2]; uint2 u; } U;
        U.h[0] = __floats2half2_rn(x.x, x.y);
        U.h[1] = __floats2half2_rn(x.z, x.w);
        ((uint2*)d)[i] = U.u;
    } else {
        const int gi = (bx - 10880) * 256 + threadIdx.x;   // [0, 229376)
        const float* W;
        int N, local;
        if (gi < 65536)       { W = w0; N = 256; local = gi; }
        else if (gi < 131072) { W = w1; N = 256; local = gi - 65536; }
        else if (gi < 163840) { W = w2; N = 128; local = gi - 131072; }
        else                  { W = w3; N = 256; local = gi - 163840; }
        const int k = local & 255, n = local >> 8;
        g_wh[gi] = __float2half(W[(size_t)k * N + n]);
    }
}

// ---------------- Sampling kernel (fp16 v, fp16 samp output) ----------------
__global__ __launch_bounds__(256)
void msda_sample(const float* __restrict__ ref, __half* __restrict__ samp)
{
    const int bq   = blockIdx.x;
    const int b    = bq / LEN_Q;
    const int h    = threadIdx.x >> 5;
    const int lane = threadIdx.x & 31;
    const int p4   = lane >> 3;
    const int cg   = lane & 7;

    const float*  off = g_off + (size_t)bq * EMBED + h * 32;
    const float*  awl = g_awl + (size_t)bq * 128 + h * 16;
    const __half* vb  = g_vh + (size_t)b * LEN_V * EMBED + h * CDIM + cg * 4;
    const float*  rp  = ref + (size_t)bq * 8;

    float4 r01 = ((const float4*)rp)[0];
    float4 r23 = ((const float4*)rp)[1];
    const float rx[4] = {r01.x, r01.z, r23.x, r23.z};
    const float ry[4] = {r01.y, r01.w, r23.y, r23.w};

    float e[4];
    e[0] = awl[p4]; e[1] = awl[4 + p4]; e[2] = awl[8 + p4]; e[3] = awl[12 + p4];
    float mx = fmaxf(fmaxf(e[0], e[1]), fmaxf(e[2], e[3]));
    mx = fmaxf(mx, __shfl_xor_sync(0xffffffffu, mx, 8));
    mx = fmaxf(mx, __shfl_xor_sync(0xffffffffu, mx, 16));
    float s = 0.f;
    #pragma unroll
    for (int l = 0; l < 4; ++l) { e[l] = __expf(e[l] - mx); s += e[l]; }
    s += __shfl_xor_sync(0xffffffffu, s, 8);
    s += __shfl_xor_sync(0xffffffffu, s, 16);
    const float inv = 1.f / s;

    const int LS[4] = {0, 4096, 5120, 5376};
    const int WI[4] = {64, 32, 16, 8};

    float4 acc = make_float4(0.f, 0.f, 0.f, 0.f);
    #pragma unroll
    for (int l = 0; l < 4; ++l) {
        const int   Wi = WI[l], ls = LS[l];
        const float Wf = (float)Wi;
        const float2 o = *(const float2*)(off + (l * 4 + p4) * 2);
        const float x = fmaf(rx[l], Wf, o.x) - 0.5f;
        const float y = fmaf(ry[l], Wf, o.y) - 0.5f;
        const float xf = floorf(x), yf = floorf(y);
        const int x0 = (int)xf, y0 = (int)yf;
        const float fx = x - xf, fy = y - yf;
        const float vx0 = ((unsigned)x0       < (unsigned)Wi) ? 1.f : 0.f;
        const float vx1 = ((unsigned)(x0 + 1) < (unsigned)Wi) ? 1.f : 0.f;
        const float vy0 = ((unsigned)y0       < (unsigned)Wi) ? 1.f : 0.f;
        const float vy1 = ((unsigned)(y0 + 1) < (unsigned)Wi) ? 1.f : 0.f;
        const int x0c = min(max(x0, 0), Wi - 1), x1c = min(max(x0 + 1, 0), Wi - 1);
        const int y0c = min(max(y0, 0), Wi - 1), y1c = min(max(y0 + 1, 0), Wi - 1);

        const float wp  = e[l] * inv;
        const float wx0 = (1.f - fx) * vx0,      wx1 = fx * vx1;
        const float wy0 = (1.f - fy) * vy0 * wp, wy1 = fy * vy1 * wp;
        const float wa = wx0 * wy0, wb = wx0 * wy1, wc = wx1 * wy0, wd = wx1 * wy1;

        const __half* row0 = vb + (size_t)(ls + y0c * Wi) * EMBED;
        const __half* row1 = vb + (size_t)(ls + y1c * Wi) * EMBED;
        const int c0 = x0c * EMBED, c1 = x1c * EMBED;

        const uint2 u00 = *(const uint2*)(row0 + c0);
        const uint2 u01 = *(const uint2*)(row0 + c1);
        const uint2 u10 = *(const uint2*)(row1 + c0);
        const uint2 u11 = *(const uint2*)(row1 + c1);

        const float2 a00 = __half22float2(*(const __half2*)&u00.x);
        const float2 b00 = __half22float2(*(const __half2*)&u00.y);
        const float2 a01 = __half22float2(*(const __half2*)&u01.x);
        const float2 b01 = __half22float2(*(const __half2*)&u01.y);
        const float2 a10 = __half22float2(*(const __half2*)&u10.x);
        const float2 b10 = __half22float2(*(const __half2*)&u10.y);
        const float2 a11 = __half22float2(*(const __half2*)&u11.x);
        const float2 b11 = __half22float2(*(const __half2*)&u11.y);

        acc.x = fmaf(wa, a00.x, fmaf(wb, a10.x, fmaf(wc, a01.x, fmaf(wd, a11.x, acc.x))));
        acc.y = fmaf(wa, a00.y, fmaf(wb, a10.y, fmaf(wc, a01.y, fmaf(wd, a11.y, acc.y))));
        acc.z = fmaf(wa, b00.x, fmaf(wb, b10.x, fmaf(wc, b01.x, fmaf(wd, b11.x, acc.z))));
        acc.w = fmaf(wa, b00.y, fmaf(wb, b10.y, fmaf(wc, b01.y, fmaf(wd, b11.y, acc.w))));
    }

    acc.x += __shfl_xor_sync(0xffffffffu, acc.x, 8);
    acc.y += __shfl_xor_sync(0xffffffffu, acc.y, 8);
    acc.z += __shfl_xor_sync(0xffffffffu, acc.z, 8);
    acc.w += __shfl_xor_sync(0xffffffffu, acc.w, 8);
    acc.x += __shfl_xor_sync(0xffffffffu, acc.x, 16);
    acc.y += __shfl_xor_sync(0xffffffffu, acc.y, 16);
    acc.z += __shfl_xor_sync(0xffffffffu, acc.z, 16);
    acc.w += __shfl_xor_sync(0xffffffffu, acc.w, 16);

    if (p4 == 0) {
        union { __half2 h[2]; uint2 u; } U;
        U.h[0] = __floats2half2_rn(acc.x, acc.y);
        U.h[1] = __floats2half2_rn(acc.z, acc.w);
        const size_t vecidx = ((size_t)bq * EMBED + h * CDIM + cg * 4) / 4;
        ((uint2*)samp)[vecidx] = U.u;
    }
}

// ---------------- Launch ----------------
extern "C" void kernel_launch(void* const* d_in, const int* in_sizes, int n_in,
                              void* d_out, int out_size)
{
    const float* query   = (const float*)d_in[0];
    const float* ref_pts = (const float*)d_in[1];
    const float* value   = (const float*)d_in[2];
    const float* vproj_w = (const float*)d_in[5];
    const float* vproj_b = (const float*)d_in[6];
    const float* off_w   = (const float*)d_in[7];
    const float* off_b   = (const float*)d_in[8];
    const float* attn_w  = (const float*)d_in[9];
    const float* attn_b  = (const float*)d_in[10];
    const float* out_w   = (const float*)d_in[11];
    const float* out_b   = (const float*)d_in[12];
    float* out = (float*)d_out;

    __half *paf0, *paf1, *pwh;
    cudaGetSymbolAddress((void**)&paf0, g_af0);
    cudaGetSymbolAddress((void**)&paf1, g_af1);
    cudaGetSymbolAddress((void**)&pwh,  g_wh);

    cudaFuncSetAttribute(gemm_proj, cudaFuncAttributeMaxDynamicSharedMemorySize, GEMM_SMEM);
    cudaFuncSetAttribute(gemm_out,  cudaFuncAttributeMaxDynamicSharedMemorySize, GEMM_SMEM);

    // fused: activations fp32->fp16 + weight transpose
    conv_fuse<<<11776, 256>>>(value, query, paf0, paf1,
                              vproj_w, off_w, attn_w, out_w);

    // merged projections: v(fp16), off(fp32), awl(fp32)
    gemm_proj<<<dim3(MROWS / 128, 5), 256, GEMM_SMEM>>>(
        paf0, paf1, pwh, vproj_b, off_b, attn_b);

    // sampling (writes fp16 samp into g_af0, already consumed by gemm_proj)
    msda_sample<<<MROWS, 256>>>(ref_pts, paf0);

    // out GEMM: out = samp @ out_w + b (fp32)
    gemm_out<<<dim3(MROWS / 128, 2), 256, GEMM_SMEM>>>(
        paf0, pwh + 163840, out_b, out);
}